// round 14
// baseline (speedup 1.0000x reference)
#include <cuda_runtime.h>
#include <cuda_bf16.h>
#include <mma.h>
#include <math.h>
#include <cstdint>

using namespace nvcuda;

#define BSZ 8
#define TD  64
#define TE  512
#define HH  512

// fp32 scratch
__device__ float g_u [BSZ*TD*HH];
__device__ float g_v [BSZ*TE*HH];
__device__ float g_cS1[4*BSZ*HH];            // colsum j-split partials
__device__ float g_cS2[4*BSZ*HH];
__device__ float g_pA[8*BSZ*TD*TE];          // split-K=8 raw partials (reused)

// bf16 hi/lo scratch
__device__ __nv_bfloat16 g_Wh [HH*2*HH],  g_Wl [HH*2*HH];
__device__ __nv_bfloat16 g_Dh [BSZ*TD*HH], g_Dl [BSZ*TD*HH];   // dec
__device__ __nv_bfloat16 g_Enh[BSZ*TE*HH], g_Enl[BSZ*TE*HH];   // enc
__device__ __nv_bfloat16 g_ETh[BSZ*HH*TE], g_ETl[BSZ*HH*TE];   // enc transposed [b,d,j]
__device__ __nv_bfloat16 g_Euh[BSZ*TD*HH], g_Eul[BSZ*TD*HH];
__device__ __nv_bfloat16 g_Evh[BSZ*TE*HH], g_Evl[BSZ*TE*HH];
__device__ __nv_bfloat16 g_Lh [BSZ*TD*TE], g_Ll [BSZ*TD*TE];   // lse hi/lo

__device__ __forceinline__ void cvt2(float x, __nv_bfloat16& h, __nv_bfloat16& l) {
    h = __float2bfloat16(x);
    l = __float2bfloat16(x - __bfloat162float(h));
}

__device__ __forceinline__ unsigned int s2u(const void* p) {
    return (unsigned int)__cvta_generic_to_shared(p);
}
__device__ __forceinline__ void cpa16(unsigned int d, const void* s) {
    asm volatile("cp.async.cg.shared.global [%0], [%1], 16;\n" :: "r"(d), "l"(s));
}
#define CP_COMMIT() asm volatile("cp.async.commit_group;\n" ::: "memory")
#define CP_WAIT0()  asm volatile("cp.async.wait_group 0;\n" ::: "memory")
#define CP_WAIT1()  asm volatile("cp.async.wait_group 1;\n" ::: "memory")

// ---------------------------------------------------------------------------
// Fused prep: blocks [0, NB_CVT) convert W/dec/enc to hi/lo bf16;
// blocks [NB_CVT, NB_CVT+NB_ET) build encT hi/lo [b,d,j].
// ---------------------------------------------------------------------------
#define N_W   (HH*2*HH)          // 524288
#define N_D   (BSZ*TD*HH)        // 262144
#define N_E   (BSZ*TE*HH)        // 2097152
#define NB_CVT ((N_W + N_D + N_E) / 1024)     // 2816
#define NB_ET  ((HH/32)*(TE/32)*BSZ)          // 2048

__global__ void __launch_bounds__(256) prep_k(
    const float* __restrict__ W, const float* __restrict__ dec,
    const float* __restrict__ enc)
{
    const int bid = blockIdx.x;
    const int tid = threadIdx.x;
    if (bid < NB_CVT) {
        long i = ((long)bid * 256 + tid) * 4;
        const float* src; __nv_bfloat16 *H, *L;
        if (i < N_W)            { src = W + i;                    H = g_Wh + i;  L = g_Wl + i; }
        else if (i < N_W + N_D) { long o = i - N_W;       src = dec + o; H = g_Dh + o;  L = g_Dl + o; }
        else                    { long o = i - N_W - N_D; src = enc + o; H = g_Enh + o; L = g_Enl + o; }
        float4 x = *reinterpret_cast<const float4*>(src);
        __nv_bfloat16 h0,h1,h2,h3,l0,l1,l2,l3;
        cvt2(x.x,h0,l0); cvt2(x.y,h1,l1); cvt2(x.z,h2,l2); cvt2(x.w,h3,l3);
        reinterpret_cast<__nv_bfloat162*>(H)[0] = __nv_bfloat162(h0,h1);
        reinterpret_cast<__nv_bfloat162*>(H)[1] = __nv_bfloat162(h2,h3);
        reinterpret_cast<__nv_bfloat162*>(L)[0] = __nv_bfloat162(l0,l1);
        reinterpret_cast<__nv_bfloat162*>(L)[1] = __nv_bfloat162(l2,l3);
    } else {
        __shared__ float t[32][33];
        const int eb  = bid - NB_CVT;
        const int b   = eb >> 8;
        const int rem = eb & 255;
        const int j0  = (rem >> 4) * 32;
        const int d0  = (rem & 15) * 32;
        const int tx = tid & 31, ty = tid >> 5;
        const float* e = enc + (long)b * TE * HH;
        #pragma unroll
        for (int p = 0; p < 4; ++p)
            t[ty + p*8][tx] = e[(long)(j0 + ty + p*8) * HH + d0 + tx];
        __syncthreads();
        #pragma unroll
        for (int p = 0; p < 4; ++p) {
            int d = d0 + ty + p*8;
            float x = t[tx][ty + p*8];
            __nv_bfloat16 h, l; cvt2(x, h, l);
            long o = (long)b * HH * TE + (long)d * TE + j0 + tx;
            g_ETh[o] = h; g_ETl[o] = l;
        }
    }
}

// ---------------------------------------------------------------------------
// Big-GEMM body (256 thr): C = A @ B^T, 128x64 CTA tile, BK=32, 4x2 warps,
// warp tile 32x32, cp.async double-buffered. C1 = acc (+bias); Ex = hilo(exp).
// ---------------------------------------------------------------------------
__device__ __forceinline__ void gemm_big(
    char* dsm,
    const __nv_bfloat16* Ah, const __nv_bfloat16* Al, int lda,
    const __nv_bfloat16* Bh, const __nv_bfloat16* Bl, int ldb,
    float* C1, int ldc,
    __nv_bfloat16* Exh, __nv_bfloat16* Exl,
    int K, const float* bias,
    int bx, int by)
{
    constexpr int BKP = 40;
    constexpr int MT  = 128;
    __nv_bfloat16* As = reinterpret_cast<__nv_bfloat16*>(dsm);
    __nv_bfloat16* Bs = As + 2*2*MT*BKP;
    float* Cs = reinterpret_cast<float*>(dsm);

    const int tid = threadIdx.x;
    const int wid = tid >> 5;
    const int wr  = wid >> 1, wc = wid & 1;
    const int nslab = K / 32;

    const __nv_bfloat16* Ah0 = Ah + (long)(by*MT)*lda;
    const __nv_bfloat16* Al0 = Al + (long)(by*MT)*lda;
    const __nv_bfloat16* Bh0 = Bh + (long)(bx*64)*ldb;
    const __nv_bfloat16* Bl0 = Bl + (long)(bx*64)*ldb;

    const int ar = tid >> 2, ac = (tid & 3) * 8;

    wmma::fragment<wmma::accumulator, 16, 16, 16, float> acc[2][2];
    #pragma unroll
    for (int i = 0; i < 2; ++i)
        #pragma unroll
        for (int j = 0; j < 2; ++j)
            wmma::fill_fragment(acc[i][j], 0.0f);

    #define STAGE_B(d, k0) do {                                                           \
        _Pragma("unroll")                                                                 \
        for (int p = 0; p < 2; ++p) {                                                     \
            int rr = ar + p*64;                                                           \
            cpa16(s2u(As + ((d)*2+0)*MT*BKP + rr*BKP + ac), Ah0 + (long)rr*lda + (k0) + ac); \
            cpa16(s2u(As + ((d)*2+1)*MT*BKP + rr*BKP + ac), Al0 + (long)rr*lda + (k0) + ac); \
        }                                                                                 \
        cpa16(s2u(Bs + ((d)*2+0)*64*BKP + ar*BKP + ac), Bh0 + (long)ar*ldb + (k0) + ac);  \
        cpa16(s2u(Bs + ((d)*2+1)*64*BKP + ar*BKP + ac), Bl0 + (long)ar*ldb + (k0) + ac);  \
    } while (0)

    STAGE_B(0, 0);
    CP_COMMIT();

    for (int s = 0; s < nslab; ++s) {
        const int d = s & 1;
        if (s + 1 < nslab) {
            STAGE_B(1 - d, (s + 1) * 32);
            CP_COMMIT();
            CP_WAIT1();
        } else {
            CP_WAIT0();
        }
        __syncthreads();

        const __nv_bfloat16* a_h = As + (d*2+0)*MT*BKP;
        const __nv_bfloat16* a_l = As + (d*2+1)*MT*BKP;
        const __nv_bfloat16* b_h = Bs + (d*2+0)*64*BKP;
        const __nv_bfloat16* b_l = Bs + (d*2+1)*64*BKP;

        #pragma unroll
        for (int k2 = 0; k2 < 32; k2 += 16) {
            wmma::fragment<wmma::matrix_a, 16, 16, 16, __nv_bfloat16, wmma::row_major> fah[2], fal[2];
            wmma::fragment<wmma::matrix_b, 16, 16, 16, __nv_bfloat16, wmma::col_major> fbh[2], fbl[2];
            #pragma unroll
            for (int i = 0; i < 2; ++i) {
                wmma::load_matrix_sync(fah[i], a_h + (wr*32 + 16*i)*BKP + k2, BKP);
                wmma::load_matrix_sync(fal[i], a_l + (wr*32 + 16*i)*BKP + k2, BKP);
            }
            #pragma unroll
            for (int j = 0; j < 2; ++j) {
                wmma::load_matrix_sync(fbh[j], b_h + (wc*32 + 16*j)*BKP + k2, BKP);
                wmma::load_matrix_sync(fbl[j], b_l + (wc*32 + 16*j)*BKP + k2, BKP);
            }
            #pragma unroll
            for (int i = 0; i < 2; ++i)
                #pragma unroll
                for (int j = 0; j < 2; ++j) {
                    wmma::mma_sync(acc[i][j], fah[i], fbh[j], acc[i][j]);
                    wmma::mma_sync(acc[i][j], fah[i], fbl[j], acc[i][j]);
                    wmma::mma_sync(acc[i][j], fal[i], fbh[j], acc[i][j]);
                }
        }
        __syncthreads();
    }
    #undef STAGE_B

    const int m0 = by * MT, n0 = bx * 64;

    #pragma unroll
    for (int i = 0; i < 2; ++i)
        #pragma unroll
        for (int j = 0; j < 2; ++j)
            wmma::store_matrix_sync(&Cs[(wr*32 + 16*i)*68 + wc*32 + 16*j],
                                    acc[i][j], 68, wmma::mem_row_major);
    __syncthreads();
    #pragma unroll
    for (int q = 0; q < 8; ++q) {
        int idx = (tid + q*256) * 4;
        int r = idx >> 6, c = idx & 63;
        float4 vv = *reinterpret_cast<float4*>(&Cs[r*68 + c]);
        if (bias) {
            vv.x += bias[n0 + c + 0]; vv.y += bias[n0 + c + 1];
            vv.z += bias[n0 + c + 2]; vv.w += bias[n0 + c + 3];
        }
        long gi = (long)(m0 + r) * ldc + n0 + c;
        *reinterpret_cast<float4*>(&C1[gi]) = vv;
        __nv_bfloat16 h0,h1,h2,h3,l0,l1,l2,l3;
        cvt2(expf(vv.x),h0,l0); cvt2(expf(vv.y),h1,l1);
        cvt2(expf(vv.z),h2,l2); cvt2(expf(vv.w),h3,l3);
        reinterpret_cast<__nv_bfloat162*>(&Exh[gi])[0] = __nv_bfloat162(h0,h1);
        reinterpret_cast<__nv_bfloat162*>(&Exh[gi])[1] = __nv_bfloat162(h2,h3);
        reinterpret_cast<__nv_bfloat162*>(&Exl[gi])[0] = __nv_bfloat162(l0,l1);
        reinterpret_cast<__nv_bfloat162*>(&Exl[gi])[1] = __nv_bfloat162(l2,l3);
    }
}

// Fused GEMM1 (y<4: u = dec@W_dec^T + bias, M=512) + GEMM2 (y>=4: v = enc@W_enc^T,
// M=4096), 128x64 tiles, exp epilogues. grid (8, 36).
__global__ void __launch_bounds__(256, 2) gemm12_k(const float* __restrict__ bias)
{
    extern __shared__ char dsm[];
    if (blockIdx.y < 4)
        gemm_big(dsm, g_Dh, g_Dl, HH, g_Wh, g_Wl, 2*HH,
                 g_u, HH, g_Euh, g_Eul, HH, bias, blockIdx.x, blockIdx.y);
    else
        gemm_big(dsm, g_Enh, g_Enl, HH, g_Wh + HH, g_Wl + HH, 2*HH,
                 g_v, HH, g_Evh, g_Evl, HH, nullptr, blockIdx.x, blockIdx.y - 4);
}

// ---------------------------------------------------------------------------
// Small-GEMM body (128 thr): raw split-K partial, 64x64 CTA tile, 2x2 warps,
// warp tile 32x32 (12 mma : 8 frag-loads per k2), BK=32, double-buffered.
// Writes acc to C1 + kz*partStride (direct wmma gmem store). M-tile is by=0.
// ---------------------------------------------------------------------------
template<int SPLITK>
__device__ __forceinline__ void gemm_small(
    char* dsm,
    const __nv_bfloat16* Ah, const __nv_bfloat16* Al, int lda, long sA,
    const __nv_bfloat16* Bh, const __nv_bfloat16* Bl, int ldb, long sB,
    float* C1, int ldc, long sC, long partStride,
    int K, int bx, int bz)
{
    constexpr int BKP = 40;
    __nv_bfloat16* As = reinterpret_cast<__nv_bfloat16*>(dsm);
    __nv_bfloat16* Bs = As + 2*2*64*BKP;

    const int tid = threadIdx.x;
    const int wid = tid >> 5;
    const int wr  = wid >> 1, wc = wid & 1;
    const int bb = bz / SPLITK, kz = bz % SPLITK;
    const int Ks = K / SPLITK, kbase = kz * Ks, nslab = Ks / 32;

    const __nv_bfloat16* Ah0 = Ah + (long)bb*sA + kbase;
    const __nv_bfloat16* Al0 = Al + (long)bb*sA + kbase;
    const __nv_bfloat16* Bh0 = Bh + (long)bb*sB + (long)(bx*64)*ldb + kbase;
    const __nv_bfloat16* Bl0 = Bl + (long)bb*sB + (long)(bx*64)*ldb + kbase;

    const int ar = tid >> 2, ac = (tid & 3) * 8;   // ar 0..31

    wmma::fragment<wmma::accumulator, 16, 16, 16, float> acc[2][2];
    #pragma unroll
    for (int i = 0; i < 2; ++i)
        #pragma unroll
        for (int j = 0; j < 2; ++j)
            wmma::fill_fragment(acc[i][j], 0.0f);

    #define STAGE_S(d, k0) do {                                                           \
        _Pragma("unroll")                                                                 \
        for (int p = 0; p < 2; ++p) {                                                     \
            int rr = ar + p*32;                                                           \
            cpa16(s2u(As + ((d)*2+0)*64*BKP + rr*BKP + ac), Ah0 + (long)rr*lda + (k0) + ac); \
            cpa16(s2u(As + ((d)*2+1)*64*BKP + rr*BKP + ac), Al0 + (long)rr*lda + (k0) + ac); \
            cpa16(s2u(Bs + ((d)*2+0)*64*BKP + rr*BKP + ac), Bh0 + (long)rr*ldb + (k0) + ac); \
            cpa16(s2u(Bs + ((d)*2+1)*64*BKP + rr*BKP + ac), Bl0 + (long)rr*ldb + (k0) + ac); \
        }                                                                                 \
    } while (0)

    STAGE_S(0, 0);
    CP_COMMIT();

    for (int s = 0; s < nslab; ++s) {
        const int d = s & 1;
        if (s + 1 < nslab) {
            STAGE_S(1 - d, (s + 1) * 32);
            CP_COMMIT();
            CP_WAIT1();
        } else {
            CP_WAIT0();
        }
        __syncthreads();

        const __nv_bfloat16* a_h = As + (d*2+0)*64*BKP;
        const __nv_bfloat16* a_l = As + (d*2+1)*64*BKP;
        const __nv_bfloat16* b_h = Bs + (d*2+0)*64*BKP;
        const __nv_bfloat16* b_l = Bs + (d*2+1)*64*BKP;

        #pragma unroll
        for (int k2 = 0; k2 < 32; k2 += 16) {
            wmma::fragment<wmma::matrix_a, 16, 16, 16, __nv_bfloat16, wmma::row_major> fah[2], fal[2];
            wmma::fragment<wmma::matrix_b, 16, 16, 16, __nv_bfloat16, wmma::col_major> fbh[2], fbl[2];
            #pragma unroll
            for (int i = 0; i < 2; ++i) {
                wmma::load_matrix_sync(fah[i], a_h + (wr*32 + 16*i)*BKP + k2, BKP);
                wmma::load_matrix_sync(fal[i], a_l + (wr*32 + 16*i)*BKP + k2, BKP);
            }
            #pragma unroll
            for (int j = 0; j < 2; ++j) {
                wmma::load_matrix_sync(fbh[j], b_h + (wc*32 + 16*j)*BKP + k2, BKP);
                wmma::load_matrix_sync(fbl[j], b_l + (wc*32 + 16*j)*BKP + k2, BKP);
            }
            #pragma unroll
            for (int i = 0; i < 2; ++i)
                #pragma unroll
                for (int j = 0; j < 2; ++j) {
                    wmma::mma_sync(acc[i][j], fah[i], fbh[j], acc[i][j]);
                    wmma::mma_sync(acc[i][j], fah[i], fbl[j], acc[i][j]);
                    wmma::mma_sync(acc[i][j], fal[i], fbh[j], acc[i][j]);
                }
        }
        __syncthreads();
    }
    #undef STAGE_S

    float* Cp = C1 + (long)kz * partStride + (long)bb * sC;
    const int n0 = bx * 64;
    #pragma unroll
    for (int i = 0; i < 2; ++i)
        #pragma unroll
        for (int j = 0; j < 2; ++j)
            wmma::store_matrix_sync(
                &Cp[(long)(wr*32 + 16*i) * ldc + n0 + wc*32 + 16*j],
                acc[i][j], ldc, wmma::mem_row_major);
}

// ---------------------------------------------------------------------------
// Fused: blocks [0,512) = P[b,i,j] = Eu.Ev split-K=8 raw partials;
//        blocks [512,1024) = colsum j-split partials. 128 threads.
// ---------------------------------------------------------------------------
__global__ void __launch_bounds__(128) gemm4_colsum_k(
    const float* __restrict__ enc)
{
    extern __shared__ char dsm[];
    const int bid = blockIdx.x;
    const int tid = threadIdx.x;
    if (bid < 512) {
        gemm_small<8>(dsm, g_Euh, g_Eul, HH, (long)TD*HH, g_Evh, g_Evl, HH, (long)TE*HH,
                      g_pA, TE, (long)TD*TE, (long)BSZ*TD*TE, HH,
                      bid & 7, bid >> 3);
    } else {
        const int cb   = bid - 512;
        const int g    = cb >> 7;
        const int rem  = cb & 127;
        const int b    = rem >> 4;
        const int dblk = rem & 15;
        const int lane = tid & 31, jg = tid >> 5;   // jg 0..3
        const int d    = dblk * 32 + lane;
        const float* e  = enc + (long)b * TE * HH + d;
        const float* vv = g_v + (long)b * TE * HH + d;
        float s1 = 0.f, s2 = 0.f;
        const int j0 = g * 128;
        #pragma unroll 8
        for (int j = j0 + jg; j < j0 + 128; j += 4) {
            float ev = e[(long)j * HH];
            s1 += ev;
            s2 += vv[(long)j * HH] * ev;
        }
        float* sh1 = reinterpret_cast<float*>(dsm);     // [4][32]
        float* sh2 = sh1 + 128;
        sh1[jg*32 + lane] = s1; sh2[jg*32 + lane] = s2;
        __syncthreads();
        if (jg == 0) {
            float t1 = 0.f, t2 = 0.f;
            #pragma unroll
            for (int q = 0; q < 4; ++q) { t1 += sh1[q*32 + lane]; t2 += sh2[q*32 + lane]; }
            g_cS1[g*BSZ*HH + b*HH + d] = t1;
            g_cS2[g*BSZ*HH + b*HH + d] = t2;
        }
    }
}

// Q[b,i,d] = lse[b,i,:] . encT[b,d,:]  raw partials, split-K=8. grid (8,1,64), 128 thr.
__global__ void __launch_bounds__(128) gemm6_k()
{
    extern __shared__ char dsm[];
    gemm_small<8>(dsm, g_Lh, g_Ll, TE, (long)TD*TE, g_ETh, g_ETl, TE, (long)HH*TE,
                  g_pA, HH, (long)TD*HH, (long)BSZ*TD*HH, TE,
                  blockIdx.x, blockIdx.z);
}

// lse = log(sum of 8 partials) -> hi/lo bf16
__global__ void __launch_bounds__(128) lse_comb(const float* __restrict__ p)
{
    const long N = (long)BSZ*TD*TE;
    long i = ((long)blockIdx.x * 128 + threadIdx.x) * 4;
    float4 s = make_float4(0.f, 0.f, 0.f, 0.f);
    #pragma unroll
    for (int g = 0; g < 8; ++g) {
        float4 a = *reinterpret_cast<const float4*>(&p[i + g*N]);
        s.x += a.x; s.y += a.y; s.z += a.z; s.w += a.w;
    }
    __nv_bfloat16 h0,h1,h2,h3,l0,l1,l2,l3;
    cvt2(logf(s.x), h0,l0); cvt2(logf(s.y), h1,l1);
    cvt2(logf(s.z), h2,l2); cvt2(logf(s.w), h3,l3);
    reinterpret_cast<__nv_bfloat162*>(&g_Lh[i])[0] = __nv_bfloat162(h0,h1);
    reinterpret_cast<__nv_bfloat162*>(&g_Lh[i])[1] = __nv_bfloat162(h2,h3);
    reinterpret_cast<__nv_bfloat162*>(&g_Ll[i])[0] = __nv_bfloat162(l0,l1);
    reinterpret_cast<__nv_bfloat162*>(&g_Ll[i])[1] = __nv_bfloat162(l2,l3);
}

// out = u*(sum cS1) + (sum cS2) - sum of 8 Q partials
__global__ void __launch_bounds__(128) final_comb(
    const float* __restrict__ p, const float* __restrict__ u,
    float* __restrict__ out)
{
    const long N = (long)BSZ*TD*HH;
    long i = ((long)blockIdx.x * 128 + threadIdx.x) * 4;
    int b = (int)(i >> 15);
    int d = (int)(i & (HH - 1));
    float4 q = make_float4(0.f, 0.f, 0.f, 0.f);
    #pragma unroll
    for (int g = 0; g < 8; ++g) {
        float4 a = *reinterpret_cast<const float4*>(&p[i + g*N]);
        q.x += a.x; q.y += a.y; q.z += a.z; q.w += a.w;
    }
    float4 uu = *reinterpret_cast<const float4*>(&u[i]);
    float4 s1 = make_float4(0.f,0.f,0.f,0.f), s2 = make_float4(0.f,0.f,0.f,0.f);
    #pragma unroll
    for (int g = 0; g < 4; ++g) {
        float4 x1 = *reinterpret_cast<const float4*>(&g_cS1[g*BSZ*HH + b*HH + d]);
        float4 x2 = *reinterpret_cast<const float4*>(&g_cS2[g*BSZ*HH + b*HH + d]);
        s1.x += x1.x; s1.y += x1.y; s1.z += x1.z; s1.w += x1.w;
        s2.x += x2.x; s2.y += x2.y; s2.z += x2.z; s2.w += x2.w;
    }
    float4 o;
    o.x = uu.x*s1.x + s2.x - q.x;
    o.y = uu.y*s1.y + s2.y - q.y;
    o.z = uu.z*s1.z + s2.z - q.z;
    o.w = uu.w*s1.w + s2.w - q.w;
    *reinterpret_cast<float4*>(&out[i]) = o;
}

// ---------------------------------------------------------------------------
extern "C" void kernel_launch(void* const* d_in, const int* in_sizes, int n_in,
                              void* d_out, int out_size)
{
    const float *enc = nullptr, *dec = nullptr, *W = nullptr, *bias = nullptr;
    for (int i = 0; i < n_in; ++i) {
        switch (in_sizes[i]) {
            case BSZ*TE*HH: enc  = (const float*)d_in[i]; break;
            case BSZ*TD*HH: dec  = (const float*)d_in[i]; break;
            case HH*2*HH:   W    = (const float*)d_in[i]; break;
            case HH:        bias = (const float*)d_in[i]; break;
        }
    }
    float* out = (float*)d_out;

    float *u, *pA;
    cudaGetSymbolAddress((void**)&u,  g_u);
    cudaGetSymbolAddress((void**)&pA, g_pA);

    constexpr int SMB64  = 2*2*(64 + 64)  * 40 * 2;   // 40960
    constexpr int SMB128 = 2*2*(128 + 64) * 40 * 2;   // 61440
    cudaFuncSetAttribute(gemm12_k, cudaFuncAttributeMaxDynamicSharedMemorySize, SMB128);

    // 0) convert W, dec, enc to hi/lo bf16 + build encT (fused)
    prep_k<<<NB_CVT + NB_ET, 256>>>(W, dec, enc);

    // 1+2) fused (128x64 tiles): u = dec@W_dec^T + bias, Eu=exp(u); v = enc@W_enc^T, Ev=exp(v)
    gemm12_k<<<dim3(8, 4 + 32, 1), 256, SMB128>>>(bias);

    // 3+4) fused: P = Eu.Ev partials (split-K=8, 128thr) + colsum j-split partials
    gemm4_colsum_k<<<512 + 512, 128, SMB64>>>(enc);

    // 5) lse = log(sum of 8 partials) -> hi/lo bf16
    lse_comb<<<(BSZ*TD*TE)/512, 128>>>(pA);

    // 6) Q = lse . encT partials (split-K=8, 128thr)
    gemm6_k<<<dim3(8, 1, BSZ*8), 128, SMB64>>>();

    // 7) out = u*S1 + S2 - sum of 8 partials
    final_comb<<<(BSZ*TD*HH)/512, 128>>>(pA, u, out);
}

// round 15
// speedup vs baseline: 1.4897x; 1.4897x over previous
#include <cuda_runtime.h>
#include <cuda_bf16.h>
#include <mma.h>
#include <math.h>
#include <cstdint>

using namespace nvcuda;

#define BSZ 8
#define TD  64
#define TE  512
#define HH  512

// fp32 scratch
__device__ float g_u [BSZ*TD*HH];
__device__ float g_v [BSZ*TE*HH];
__device__ float g_cS1[4*BSZ*HH];            // colsum j-split partials
__device__ float g_cS2[4*BSZ*HH];
__device__ float g_pA[8*BSZ*TD*TE];          // split-K=8 raw partials (reused)

// bf16 hi/lo scratch
__device__ __nv_bfloat16 g_Wh [HH*2*HH],  g_Wl [HH*2*HH];
__device__ __nv_bfloat16 g_Dh [BSZ*TD*HH], g_Dl [BSZ*TD*HH];   // dec
__device__ __nv_bfloat16 g_Enh[BSZ*TE*HH], g_Enl[BSZ*TE*HH];   // enc
__device__ __nv_bfloat16 g_ETh[BSZ*HH*TE], g_ETl[BSZ*HH*TE];   // enc transposed [b,d,j]
__device__ __nv_bfloat16 g_Euh[BSZ*TD*HH], g_Eul[BSZ*TD*HH];
__device__ __nv_bfloat16 g_Evh[BSZ*TE*HH], g_Evl[BSZ*TE*HH];
__device__ __nv_bfloat16 g_Lh [BSZ*TD*TE], g_Ll [BSZ*TD*TE];   // lse hi/lo

__device__ __forceinline__ void cvt2(float x, __nv_bfloat16& h, __nv_bfloat16& l) {
    h = __float2bfloat16(x);
    l = __float2bfloat16(x - __bfloat162float(h));
}

__device__ __forceinline__ unsigned int s2u(const void* p) {
    return (unsigned int)__cvta_generic_to_shared(p);
}
__device__ __forceinline__ void cpa16(unsigned int d, const void* s) {
    asm volatile("cp.async.cg.shared.global [%0], [%1], 16;\n" :: "r"(d), "l"(s));
}
#define CP_COMMIT() asm volatile("cp.async.commit_group;\n" ::: "memory")
#define CP_WAIT0()  asm volatile("cp.async.wait_group 0;\n" ::: "memory")
#define CP_WAIT1()  asm volatile("cp.async.wait_group 1;\n" ::: "memory")

// ---------------------------------------------------------------------------
// Fused prep: blocks [0, NB_CVT) convert W/dec/enc to hi/lo bf16;
// blocks [NB_CVT, NB_CVT+NB_ET) build encT hi/lo [b,d,j].
// ---------------------------------------------------------------------------
#define N_W   (HH*2*HH)          // 524288
#define N_D   (BSZ*TD*HH)        // 262144
#define N_E   (BSZ*TE*HH)        // 2097152
#define NB_CVT ((N_W + N_D + N_E) / 1024)     // 2816
#define NB_ET  ((HH/32)*(TE/32)*BSZ)          // 2048

__global__ void __launch_bounds__(256) prep_k(
    const float* __restrict__ W, const float* __restrict__ dec,
    const float* __restrict__ enc)
{
    const int bid = blockIdx.x;
    const int tid = threadIdx.x;
    if (bid < NB_CVT) {
        long i = ((long)bid * 256 + tid) * 4;
        const float* src; __nv_bfloat16 *H, *L;
        if (i < N_W)            { src = W + i;                    H = g_Wh + i;  L = g_Wl + i; }
        else if (i < N_W + N_D) { long o = i - N_W;       src = dec + o; H = g_Dh + o;  L = g_Dl + o; }
        else                    { long o = i - N_W - N_D; src = enc + o; H = g_Enh + o; L = g_Enl + o; }
        float4 x = *reinterpret_cast<const float4*>(src);
        __nv_bfloat16 h0,h1,h2,h3,l0,l1,l2,l3;
        cvt2(x.x,h0,l0); cvt2(x.y,h1,l1); cvt2(x.z,h2,l2); cvt2(x.w,h3,l3);
        reinterpret_cast<__nv_bfloat162*>(H)[0] = __nv_bfloat162(h0,h1);
        reinterpret_cast<__nv_bfloat162*>(H)[1] = __nv_bfloat162(h2,h3);
        reinterpret_cast<__nv_bfloat162*>(L)[0] = __nv_bfloat162(l0,l1);
        reinterpret_cast<__nv_bfloat162*>(L)[1] = __nv_bfloat162(l2,l3);
    } else {
        __shared__ float t[32][33];
        const int eb  = bid - NB_CVT;
        const int b   = eb >> 8;
        const int rem = eb & 255;
        const int j0  = (rem >> 4) * 32;
        const int d0  = (rem & 15) * 32;
        const int tx = tid & 31, ty = tid >> 5;
        const float* e = enc + (long)b * TE * HH;
        #pragma unroll
        for (int p = 0; p < 4; ++p)
            t[ty + p*8][tx] = e[(long)(j0 + ty + p*8) * HH + d0 + tx];
        __syncthreads();
        #pragma unroll
        for (int p = 0; p < 4; ++p) {
            int d = d0 + ty + p*8;
            float x = t[tx][ty + p*8];
            __nv_bfloat16 h, l; cvt2(x, h, l);
            long o = (long)b * HH * TE + (long)d * TE + j0 + tx;
            g_ETh[o] = h; g_ETl[o] = l;
        }
    }
}

// ---------------------------------------------------------------------------
// hi/lo bf16 GEMM body, C = A @ B^T, CTA tile MT x 64, BK=32, 256 threads,
// cp.async double-buffered. (R12 body, unchanged.)
// MODE 0: C1 = acc (+bias[col]); Exh/Exl = hilo(exp(C1))
// MODE 1: raw partial -> C1 + kz*partStride (direct wmma gmem store)
// ---------------------------------------------------------------------------
template<int MT, int MODE, int SPLITK>
__device__ __forceinline__ void gemm_body(
    char* dsm,
    const __nv_bfloat16* Ah, const __nv_bfloat16* Al, int lda, long sA,
    const __nv_bfloat16* Bh, const __nv_bfloat16* Bl, int ldb, long sB,
    float* C1, int ldc, long sC, long partStride,
    __nv_bfloat16* Exh, __nv_bfloat16* Exl,
    int K, const float* bias,
    int bx, int by, int bz)
{
    constexpr int BKP = 40;
    constexpr int NJ  = (MT == 128) ? 2 : 1;
    __nv_bfloat16* As = reinterpret_cast<__nv_bfloat16*>(dsm);
    __nv_bfloat16* Bs = As + 2*2*MT*BKP;
    float* Cs = reinterpret_cast<float*>(dsm);

    const int tid = threadIdx.x;
    const int wid = tid >> 5;
    const int wr  = (MT == 128) ? (wid >> 1) : (wid >> 2);
    const int wc  = (MT == 128) ? (wid & 1)  : (wid & 3);
    const int bb = bz / SPLITK, kz = bz % SPLITK;
    const int Ks = K / SPLITK, kbase = kz * Ks, nslab = Ks / 32;

    const __nv_bfloat16* Ah0 = Ah + (long)bb*sA + (long)(by*MT)*lda + kbase;
    const __nv_bfloat16* Al0 = Al + (long)bb*sA + (long)(by*MT)*lda + kbase;
    const __nv_bfloat16* Bh0 = Bh + (long)bb*sB + (long)(bx*64)*ldb + kbase;
    const __nv_bfloat16* Bl0 = Bl + (long)bb*sB + (long)(bx*64)*ldb + kbase;

    const int ar = tid >> 2, ac = (tid & 3) * 8;

    wmma::fragment<wmma::accumulator, 16, 16, 16, float> acc[2][NJ];
    #pragma unroll
    for (int i = 0; i < 2; ++i)
        #pragma unroll
        for (int j = 0; j < NJ; ++j)
            wmma::fill_fragment(acc[i][j], 0.0f);

    #define STAGE(d, k0) do {                                                             \
        _Pragma("unroll")                                                                 \
        for (int p = 0; p < MT/64; ++p) {                                                 \
            int rr = ar + p*64;                                                           \
            cpa16(s2u(As + ((d)*2+0)*MT*BKP + rr*BKP + ac), Ah0 + (long)rr*lda + (k0) + ac); \
            cpa16(s2u(As + ((d)*2+1)*MT*BKP + rr*BKP + ac), Al0 + (long)rr*lda + (k0) + ac); \
        }                                                                                 \
        cpa16(s2u(Bs + ((d)*2+0)*64*BKP + ar*BKP + ac), Bh0 + (long)ar*ldb + (k0) + ac);  \
        cpa16(s2u(Bs + ((d)*2+1)*64*BKP + ar*BKP + ac), Bl0 + (long)ar*ldb + (k0) + ac);  \
    } while (0)

    STAGE(0, 0);
    CP_COMMIT();

    for (int s = 0; s < nslab; ++s) {
        const int d = s & 1;
        if (s + 1 < nslab) {
            STAGE(1 - d, (s + 1) * 32);
            CP_COMMIT();
            CP_WAIT1();
        } else {
            CP_WAIT0();
        }
        __syncthreads();

        const __nv_bfloat16* a_h = As + (d*2+0)*MT*BKP;
        const __nv_bfloat16* a_l = As + (d*2+1)*MT*BKP;
        const __nv_bfloat16* b_h = Bs + (d*2+0)*64*BKP;
        const __nv_bfloat16* b_l = Bs + (d*2+1)*64*BKP;

        #pragma unroll
        for (int k2 = 0; k2 < 32; k2 += 16) {
            wmma::fragment<wmma::matrix_a, 16, 16, 16, __nv_bfloat16, wmma::row_major> fah[2], fal[2];
            wmma::fragment<wmma::matrix_b, 16, 16, 16, __nv_bfloat16, wmma::col_major> fbh[NJ], fbl[NJ];
            #pragma unroll
            for (int i = 0; i < 2; ++i) {
                wmma::load_matrix_sync(fah[i], a_h + (wr*32 + 16*i)*BKP + k2, BKP);
                wmma::load_matrix_sync(fal[i], a_l + (wr*32 + 16*i)*BKP + k2, BKP);
            }
            #pragma unroll
            for (int j = 0; j < NJ; ++j) {
                wmma::load_matrix_sync(fbh[j], b_h + (wc*(16*NJ) + 16*j)*BKP + k2, BKP);
                wmma::load_matrix_sync(fbl[j], b_l + (wc*(16*NJ) + 16*j)*BKP + k2, BKP);
            }
            #pragma unroll
            for (int i = 0; i < 2; ++i)
                #pragma unroll
                for (int j = 0; j < NJ; ++j) {
                    wmma::mma_sync(acc[i][j], fah[i], fbh[j], acc[i][j]);
                    wmma::mma_sync(acc[i][j], fah[i], fbl[j], acc[i][j]);
                    wmma::mma_sync(acc[i][j], fal[i], fbh[j], acc[i][j]);
                }
        }
        __syncthreads();
    }
    #undef STAGE

    const int m0 = by * MT, n0 = bx * 64;

    if (MODE == 1) {
        float* Cp = C1 + (long)kz * partStride + (long)bb * sC;
        #pragma unroll
        for (int i = 0; i < 2; ++i)
            #pragma unroll
            for (int j = 0; j < NJ; ++j)
                wmma::store_matrix_sync(
                    &Cp[(long)(m0 + wr*32 + 16*i) * ldc + n0 + wc*(16*NJ) + 16*j],
                    acc[i][j], ldc, wmma::mem_row_major);
    } else {
        #pragma unroll
        for (int i = 0; i < 2; ++i)
            #pragma unroll
            for (int j = 0; j < NJ; ++j)
                wmma::store_matrix_sync(&Cs[(wr*32 + 16*i)*68 + wc*(16*NJ) + 16*j],
                                        acc[i][j], 68, wmma::mem_row_major);
        __syncthreads();
        #pragma unroll
        for (int q = 0; q < (MT*64)/1024; ++q) {
            int idx = (tid + q*256) * 4;
            int r = idx >> 6, c = idx & 63;
            float4 vv = *reinterpret_cast<float4*>(&Cs[r*68 + c]);
            if (bias) {
                vv.x += bias[n0 + c + 0]; vv.y += bias[n0 + c + 1];
                vv.z += bias[n0 + c + 2]; vv.w += bias[n0 + c + 3];
            }
            long gi = (long)bb*sC + (long)(m0 + r)*ldc + n0 + c;
            *reinterpret_cast<float4*>(&C1[gi]) = vv;
            __nv_bfloat16 h0,h1,h2,h3,l0,l1,l2,l3;
            cvt2(expf(vv.x),h0,l0); cvt2(expf(vv.y),h1,l1);
            cvt2(expf(vv.z),h2,l2); cvt2(expf(vv.w),h3,l3);
            reinterpret_cast<__nv_bfloat162*>(&Exh[gi])[0] = __nv_bfloat162(h0,h1);
            reinterpret_cast<__nv_bfloat162*>(&Exh[gi])[1] = __nv_bfloat162(h2,h3);
            reinterpret_cast<__nv_bfloat162*>(&Exl[gi])[0] = __nv_bfloat162(l0,l1);
            reinterpret_cast<__nv_bfloat162*>(&Exl[gi])[1] = __nv_bfloat162(l2,l3);
        }
    }
}

// Fused GEMM1 (y<4: u = dec@W_dec^T + bias, M=512) + GEMM2 (y>=4: v = enc@W_enc^T,
// M=4096), 128x64 tiles, exp epilogues. grid (8, 36).
__global__ void __launch_bounds__(256, 2) gemm12_k(const float* __restrict__ bias)
{
    extern __shared__ char dsm[];
    if (blockIdx.y < 4)
        gemm_body<128,0,1>(dsm, g_Dh, g_Dl, HH, 0L, g_Wh, g_Wl, 2*HH, 0L,
                           g_u, HH, 0L, 0L, g_Euh, g_Eul, HH, bias,
                           blockIdx.x, blockIdx.y, 0);
    else
        gemm_body<128,0,1>(dsm, g_Enh, g_Enl, HH, 0L, g_Wh + HH, g_Wl + HH, 2*HH, 0L,
                           g_v, HH, 0L, 0L, g_Evh, g_Evl, HH, nullptr,
                           blockIdx.x, blockIdx.y - 4, 0);
}

// ---------------------------------------------------------------------------
// Fused: blocks [0,512) = P[b,i,j] = Eu.Ev split-K=8 raw partials (R12 body);
//        blocks [512,1024) = colsum j-split partials (256 thr).
// ---------------------------------------------------------------------------
__global__ void __launch_bounds__(256) gemm4_colsum_k(
    const float* __restrict__ enc)
{
    extern __shared__ char dsm[];
    const int bid = blockIdx.x;
    const int tid = threadIdx.x;
    if (bid < 512) {
        gemm_body<64,1,8>(dsm, g_Euh, g_Eul, HH, (long)TD*HH, g_Evh, g_Evl, HH, (long)TE*HH,
                          g_pA, TE, (long)TD*TE, (long)BSZ*TD*TE, nullptr, nullptr, HH, nullptr,
                          bid & 7, 0, bid >> 3);
    } else {
        const int cb   = bid - 512;
        const int g    = cb >> 7;
        const int rem  = cb & 127;
        const int b    = rem >> 4;
        const int dblk = rem & 15;
        const int lane = tid & 31, jg = tid >> 5;
        const int d    = dblk * 32 + lane;
        const float* e  = enc + (long)b * TE * HH + d;
        const float* vv = g_v + (long)b * TE * HH + d;
        float s1 = 0.f, s2 = 0.f;
        const int j0 = g * 128;
        #pragma unroll 8
        for (int j = j0 + jg; j < j0 + 128; j += 8) {
            float ev = e[(long)j * HH];
            s1 += ev;
            s2 += vv[(long)j * HH] * ev;
        }
        float* sh1 = reinterpret_cast<float*>(dsm);
        float* sh2 = sh1 + 256;
        sh1[jg*32 + lane] = s1; sh2[jg*32 + lane] = s2;
        __syncthreads();
        if (jg == 0) {
            float t1 = 0.f, t2 = 0.f;
            #pragma unroll
            for (int q = 0; q < 8; ++q) { t1 += sh1[q*32 + lane]; t2 += sh2[q*32 + lane]; }
            g_cS1[g*BSZ*HH + b*HH + d] = t1;
            g_cS2[g*BSZ*HH + b*HH + d] = t2;
        }
    }
}

// Q[b,i,d] = lse[b,i,:] . encT[b,d,:]  raw partials, split-K=8. grid (8,1,64).
__global__ void __launch_bounds__(256) gemm6_k()
{
    extern __shared__ char dsm[];
    gemm_body<64,1,8>(dsm, g_Lh, g_Ll, TE, (long)TD*TE, g_ETh, g_ETl, TE, (long)HH*TE,
                      g_pA, HH, (long)TD*HH, (long)BSZ*TD*HH, nullptr, nullptr, TE, nullptr,
                      blockIdx.x, 0, blockIdx.z);
}

// lse = log(sum of 8 partials) -> hi/lo bf16
__global__ void __launch_bounds__(128) lse_comb(const float* __restrict__ p)
{
    const long N = (long)BSZ*TD*TE;
    long i = ((long)blockIdx.x * 128 + threadIdx.x) * 4;
    float4 s = make_float4(0.f, 0.f, 0.f, 0.f);
    #pragma unroll
    for (int g = 0; g < 8; ++g) {
        float4 a = *reinterpret_cast<const float4*>(&p[i + g*N]);
        s.x += a.x; s.y += a.y; s.z += a.z; s.w += a.w;
    }
    __nv_bfloat16 h0,h1,h2,h3,l0,l1,l2,l3;
    cvt2(logf(s.x), h0,l0); cvt2(logf(s.y), h1,l1);
    cvt2(logf(s.z), h2,l2); cvt2(logf(s.w), h3,l3);
    reinterpret_cast<__nv_bfloat162*>(&g_Lh[i])[0] = __nv_bfloat162(h0,h1);
    reinterpret_cast<__nv_bfloat162*>(&g_Lh[i])[1] = __nv_bfloat162(h2,h3);
    reinterpret_cast<__nv_bfloat162*>(&g_Ll[i])[0] = __nv_bfloat162(l0,l1);
    reinterpret_cast<__nv_bfloat162*>(&g_Ll[i])[1] = __nv_bfloat162(l2,l3);
}

// out = u*(sum cS1) + (sum cS2) - sum of 8 Q partials
__global__ void __launch_bounds__(128) final_comb(
    const float* __restrict__ p, const float* __restrict__ u,
    float* __restrict__ out)
{
    const long N = (long)BSZ*TD*HH;
    long i = ((long)blockIdx.x * 128 + threadIdx.x) * 4;
    int b = (int)(i >> 15);
    int d = (int)(i & (HH - 1));
    float4 q = make_float4(0.f, 0.f, 0.f, 0.f);
    #pragma unroll
    for (int g = 0; g < 8; ++g) {
        float4 a = *reinterpret_cast<const float4*>(&p[i + g*N]);
        q.x += a.x; q.y += a.y; q.z += a.z; q.w += a.w;
    }
    float4 uu = *reinterpret_cast<const float4*>(&u[i]);
    float4 s1 = make_float4(0.f,0.f,0.f,0.f), s2 = make_float4(0.f,0.f,0.f,0.f);
    #pragma unroll
    for (int g = 0; g < 4; ++g) {
        float4 x1 = *reinterpret_cast<const float4*>(&g_cS1[g*BSZ*HH + b*HH + d]);
        float4 x2 = *reinterpret_cast<const float4*>(&g_cS2[g*BSZ*HH + b*HH + d]);
        s1.x += x1.x; s1.y += x1.y; s1.z += x1.z; s1.w += x1.w;
        s2.x += x2.x; s2.y += x2.y; s2.z += x2.z; s2.w += x2.w;
    }
    float4 o;
    o.x = uu.x*s1.x + s2.x - q.x;
    o.y = uu.y*s1.y + s2.y - q.y;
    o.z = uu.z*s1.z + s2.z - q.z;
    o.w = uu.w*s1.w + s2.w - q.w;
    *reinterpret_cast<float4*>(&out[i]) = o;
}

// ---------------------------------------------------------------------------
extern "C" void kernel_launch(void* const* d_in, const int* in_sizes, int n_in,
                              void* d_out, int out_size)
{
    const float *enc = nullptr, *dec = nullptr, *W = nullptr, *bias = nullptr;
    for (int i = 0; i < n_in; ++i) {
        switch (in_sizes[i]) {
            case BSZ*TE*HH: enc  = (const float*)d_in[i]; break;
            case BSZ*TD*HH: dec  = (const float*)d_in[i]; break;
            case HH*2*HH:   W    = (const float*)d_in[i]; break;
            case HH:        bias = (const float*)d_in[i]; break;
        }
    }
    float* out = (float*)d_out;

    float *u, *pA;
    cudaGetSymbolAddress((void**)&u,  g_u);
    cudaGetSymbolAddress((void**)&pA, g_pA);

    constexpr int SMB64  = 2*2*(64 + 64)  * 40 * 2;   // 40960
    constexpr int SMB128 = 2*2*(128 + 64) * 40 * 2;   // 61440
    cudaFuncSetAttribute(gemm12_k, cudaFuncAttributeMaxDynamicSharedMemorySize, SMB128);

    // 0) convert W, dec, enc to hi/lo bf16 + build encT (fused)
    prep_k<<<NB_CVT + NB_ET, 256>>>(W, dec, enc);

    // 1+2) fused (128x64 tiles): u = dec@W_dec^T + bias, Eu=exp(u); v = enc@W_enc^T, Ev=exp(v)
    gemm12_k<<<dim3(8, 4 + 32, 1), 256, SMB128>>>(bias);

    // 3+4) fused: P = Eu.Ev partials (split-K=8) + colsum j-split partials
    gemm4_colsum_k<<<512 + 512, 256, SMB64>>>(enc);

    // 5) lse = log(sum of 8 partials) -> hi/lo bf16
    lse_comb<<<(BSZ*TD*TE)/512, 128>>>(pA);

    // 6) Q = lse . encT partials (split-K=8)
    gemm6_k<<<dim3(8, 1, BSZ*8), 256, SMB64>>>();

    // 7) out = u*S1 + S2 - sum of 8 partials
    final_comb<<<(BSZ*TD*HH)/512, 128>>>(pA, u, out);
}